// round 2
// baseline (speedup 1.0000x reference)
#include <cuda_runtime.h>
#include <math.h>

// Problem: tensor [8192, 256] fp32.
// out = (adj @ X) where adj = rownorm(cosine_sim(X)).
// Factored: M = X_hat^T X (256x256), s = sum_j x_hat_j (256),
//           out[i] = (x_i @ M) / (x_i . s)   (inv-norm cancels).
// Denominator path in fp64: row_sum cancellation (min |row_sum| ~ 0.01 over
// 8192 rows) amplifies rounding discrepancies vs the reference; fp64 makes
// our denominator exact so only the reference's own rounding remains.

#define NROWS 8192
#define DDIM  256
#define KCHUNKS 32          // 8192 / 256 rows per gram chunk
#define SCHUNKS 64          // 8192 / 128 rows per norm/s block

__device__ float  g_invn[NROWS];
__device__ double g_spart[SCHUNKS][DDIM];
__device__ double g_sd[DDIM];
__device__ float  g_Mpart[KCHUNKS][DDIM * DDIM];
__device__ float  g_M[DDIM * DDIM];

// ---------------------------------------------------------------------------
// Kernel 1: per-row inverse norms + fp64 partial column sums of X_hat.
// 64 blocks x 256 threads; block b handles rows [b*128, b*128+128).
// ---------------------------------------------------------------------------
__global__ void k_norm_s(const float* __restrict__ X) {
    __shared__ float invn_sh[128];
    const int b    = blockIdx.x;
    const int row0 = b * 128;
    const int wid  = threadIdx.x >> 5;
    const int lane = threadIdx.x & 31;

    // 8 warps, 16 rows each: warp-level sum of squares per row.
    for (int r = wid; r < 128; r += 8) {
        const float4* p = reinterpret_cast<const float4*>(X + (size_t)(row0 + r) * DDIM);
        float ss = 0.f;
        #pragma unroll
        for (int q = 0; q < 2; q++) {
            float4 v = p[lane + q * 32];
            ss += v.x * v.x + v.y * v.y + v.z * v.z + v.w * v.w;
        }
        #pragma unroll
        for (int o = 16; o > 0; o >>= 1) ss += __shfl_xor_sync(0xffffffffu, ss, o);
        if (lane == 0) {
            float inv = 1.0f / fmaxf(sqrtf(ss), 1e-8f);
            invn_sh[r]        = inv;
            g_invn[row0 + r]  = inv;
        }
    }
    __syncthreads();

    // fp64 partial column sums of x_hat: thread t owns column t.
    const int t = threadIdx.x;
    double acc = 0.0;
    #pragma unroll 4
    for (int r = 0; r < 128; r++) {
        acc += (double)invn_sh[r] * (double)X[(size_t)(row0 + r) * DDIM + t];
    }
    g_spart[b][t] = acc;
}

// ---------------------------------------------------------------------------
// Kernel 2: partial Gram M = X_hat^T X.
// grid = (32 k-chunks, 4 tiles). Tile (ti,tj) covers M[128ti:+128, 128tj:+128].
// 256 threads, each an 8x8 register tile (rows {ty*4..+3, 64+ty*4..+3}, cols
// analogous with tx) — float4 smem loads are bank-conflict free this way.
// ---------------------------------------------------------------------------
__global__ void k_gram(const float* __restrict__ X) {
    __shared__ float SA[8][128];
    __shared__ float SB[8][128];

    const int c  = blockIdx.x;          // row chunk: rows [c*256, c*256+256)
    const int ti = blockIdx.y >> 1;
    const int tj = blockIdx.y & 1;
    const int tx = threadIdx.x & 15;
    const int ty = threadIdx.x >> 4;
    const int lrow = threadIdx.x >> 5;  // 0..7   stage row
    const int f4   = threadIdx.x & 31;  // 0..31  float4 index within 128 floats

    float T[8][8];
    #pragma unroll
    for (int i = 0; i < 8; i++)
        #pragma unroll
        for (int j = 0; j < 8; j++) T[i][j] = 0.f;

    const int rowbase = c * 256;
    for (int kk = 0; kk < 256; kk += 8) {
        const int gr = rowbase + kk + lrow;
        const float inv = g_invn[gr];
        const float4 va = *reinterpret_cast<const float4*>(X + (size_t)gr * DDIM + ti * 128 + f4 * 4);
        const float4 vb = *reinterpret_cast<const float4*>(X + (size_t)gr * DDIM + tj * 128 + f4 * 4);
        __syncthreads();   // previous iteration's reads done
        *reinterpret_cast<float4*>(&SA[lrow][f4 * 4]) =
            make_float4(va.x * inv, va.y * inv, va.z * inv, va.w * inv);
        *reinterpret_cast<float4*>(&SB[lrow][f4 * 4]) = vb;
        __syncthreads();
        #pragma unroll
        for (int r = 0; r < 8; r++) {
            float a[8], bb[8];
            *reinterpret_cast<float4*>(&a[0])  = *reinterpret_cast<const float4*>(&SA[r][ty * 4]);
            *reinterpret_cast<float4*>(&a[4])  = *reinterpret_cast<const float4*>(&SA[r][64 + ty * 4]);
            *reinterpret_cast<float4*>(&bb[0]) = *reinterpret_cast<const float4*>(&SB[r][tx * 4]);
            *reinterpret_cast<float4*>(&bb[4]) = *reinterpret_cast<const float4*>(&SB[r][64 + tx * 4]);
            #pragma unroll
            for (int i = 0; i < 8; i++)
                #pragma unroll
                for (int j = 0; j < 8; j++) T[i][j] += a[i] * bb[j];
        }
    }

    float* out = g_Mpart[c];
    #pragma unroll
    for (int i = 0; i < 8; i++) {
        const int m = ti * 128 + ((i < 4) ? (ty * 4 + i) : (64 + ty * 4 + (i - 4)));
        *reinterpret_cast<float4*>(&out[m * DDIM + tj * 128 + tx * 4]) =
            make_float4(T[i][0], T[i][1], T[i][2], T[i][3]);
        *reinterpret_cast<float4*>(&out[m * DDIM + tj * 128 + 64 + tx * 4]) =
            make_float4(T[i][4], T[i][5], T[i][6], T[i][7]);
    }
}

// ---------------------------------------------------------------------------
// Kernel 3: reduce partials (fp64 accumulation). 256 blocks x 256 threads over
// 65536 M elements; block 0's threads also fold the 64 s-partials.
// ---------------------------------------------------------------------------
__global__ void k_reduce() {
    const int idx = blockIdx.x * 256 + threadIdx.x;
    double acc = 0.0;
    #pragma unroll
    for (int c = 0; c < KCHUNKS; c++) acc += (double)g_Mpart[c][idx];
    g_M[idx] = (float)acc;
    if (blockIdx.x == 0) {
        double sa = 0.0;
        #pragma unroll
        for (int b = 0; b < SCHUNKS; b++) sa += g_spart[b][threadIdx.x];
        g_sd[threadIdx.x] = sa;
    }
}

// ---------------------------------------------------------------------------
// Kernel 4: OUT = (X @ M) / (X . s)  rowwise, denominator in fp64.
// grid = (64 row-chunks, 2 col-halves). Same 8x8 register tiling; A-panel is
// transposed into smem (pad 132 keeps both store and load phases conflict-free).
// ---------------------------------------------------------------------------
__global__ void k_out(const float* __restrict__ X, float* __restrict__ OUT) {
    __shared__ float  SA[8][132];
    __shared__ float  SB[8][128];
    __shared__ double s_sh[DDIM];
    __shared__ float  rinv_sh[128];

    const int rb   = blockIdx.x;
    const int cb   = blockIdx.y;
    const int row0 = rb * 128;
    const int tx   = threadIdx.x & 15;
    const int ty   = threadIdx.x >> 4;

    s_sh[threadIdx.x] = g_sd[threadIdx.x];
    __syncthreads();

    // Per-row 1/(x . s) in fp64: 8 warps x 16 rows.
    {
        const int wid  = threadIdx.x >> 5;
        const int lane = threadIdx.x & 31;
        for (int r = wid; r < 128; r += 8) {
            const float* xp = X + (size_t)(row0 + r) * DDIM;
            double dp = 0.0;
            #pragma unroll
            for (int q = 0; q < 8; q++) {
                int k = q * 32 + lane;
                dp += (double)xp[k] * s_sh[k];
            }
            #pragma unroll
            for (int o = 16; o > 0; o >>= 1) dp += __shfl_xor_sync(0xffffffffu, dp, o);
            if (lane == 0) rinv_sh[r] = (float)(1.0 / dp);
        }
    }

    float T[8][8];
    #pragma unroll
    for (int i = 0; i < 8; i++)
        #pragma unroll
        for (int j = 0; j < 8; j++) T[i][j] = 0.f;

    const int lr = threadIdx.x >> 1;    // 0..127: tile row this thread stages
    const int hh = threadIdx.x & 1;     // which half of the 8 k-values
    const int krow = threadIdx.x >> 5;  // SB stage row
    const int f4   = threadIdx.x & 31;

    for (int k0 = 0; k0 < 256; k0 += 8) {
        const float4 va  = *reinterpret_cast<const float4*>(X + (size_t)(row0 + lr) * DDIM + k0 + hh * 4);
        const float4 vbv = *reinterpret_cast<const float4*>(&g_M[(k0 + krow) * DDIM + cb * 128 + f4 * 4]);
        __syncthreads();
        SA[hh * 4 + 0][lr] = va.x;
        SA[hh * 4 + 1][lr] = va.y;
        SA[hh * 4 + 2][lr] = va.z;
        SA[hh * 4 + 3][lr] = va.w;
        *reinterpret_cast<float4*>(&SB[krow][f4 * 4]) = vbv;
        __syncthreads();
        #pragma unroll
        for (int r = 0; r < 8; r++) {
            float a[8], bb[8];
            *reinterpret_cast<float4*>(&a[0])  = *reinterpret_cast<const float4*>(&SA[r][ty * 4]);
            *reinterpret_cast<float4*>(&a[4])  = *reinterpret_cast<const float4*>(&SA[r][64 + ty * 4]);
            *reinterpret_cast<float4*>(&bb[0]) = *reinterpret_cast<const float4*>(&SB[r][tx * 4]);
            *reinterpret_cast<float4*>(&bb[4]) = *reinterpret_cast<const float4*>(&SB[r][64 + tx * 4]);
            #pragma unroll
            for (int i = 0; i < 8; i++)
                #pragma unroll
                for (int j = 0; j < 8; j++) T[i][j] += a[i] * bb[j];
        }
    }

    #pragma unroll
    for (int i = 0; i < 8; i++) {
        const int m = (i < 4) ? (ty * 4 + i) : (64 + ty * 4 + (i - 4));
        const float rv = rinv_sh[m];
        *reinterpret_cast<float4*>(&OUT[(size_t)(row0 + m) * DDIM + cb * 128 + tx * 4]) =
            make_float4(T[i][0] * rv, T[i][1] * rv, T[i][2] * rv, T[i][3] * rv);
        *reinterpret_cast<float4*>(&OUT[(size_t)(row0 + m) * DDIM + cb * 128 + 64 + tx * 4]) =
            make_float4(T[i][4] * rv, T[i][5] * rv, T[i][6] * rv, T[i][7] * rv);
    }
}

extern "C" void kernel_launch(void* const* d_in, const int* in_sizes, int n_in,
                              void* d_out, int out_size) {
    (void)in_sizes; (void)n_in; (void)out_size;
    const float* X = (const float*)d_in[0];
    float* OUT     = (float*)d_out;

    k_norm_s<<<SCHUNKS, 256>>>(X);
    k_gram<<<dim3(KCHUNKS, 4), 256>>>(X);
    k_reduce<<<256, 256>>>();
    k_out<<<dim3(64, 2), 256>>>(X, OUT);
}